// round 1
// baseline (speedup 1.0000x reference)
#include <cuda_runtime.h>
#include <cuda_bf16.h>

// ---------------------------------------------------------------------------
// Problem constants (fixed by the dataset)
// ---------------------------------------------------------------------------
#define S_LEN   256
#define BSZ     64
#define IN_DIM  128
#define HID     128
#define NT      2
#define TAPELEN 128
#define DIM     64          // HID / NT
#define LH      64          // HID / 2
#define G4      256         // 4 * LH

#define N_ROWS  (S_LEN * BSZ)          // 16384

// d_out layout: outputs [S,B,HID], tape [TL,B,NT,DIM], rpos [TL,B,NT], wpos [TL,B,NT]
#define OUT_OUTPUTS_OFF 0
#define OUT_OUTPUTS_SZ  (S_LEN * BSZ * HID)                 // 2097152
#define OUT_TAPE_OFF    (OUT_OUTPUTS_SZ)                    // 2097152
#define OUT_TAPE_SZ     (TAPELEN * BSZ * NT * DIM)          // 1048576
#define OUT_RPOS_OFF    (OUT_TAPE_OFF + OUT_TAPE_SZ)        // 3145728
#define OUT_POS_SZ      (TAPELEN * BSZ * NT)                // 16384
#define OUT_WPOS_OFF    (OUT_RPOS_OFF + OUT_POS_SZ)         // 3162112
#define OUT_TOTAL       (OUT_WPOS_OFF + OUT_POS_SZ)         // 3178496

typedef unsigned long long u64;

// ---------------------------------------------------------------------------
// f32x2 packed-math helpers (Blackwell FFMA2 path — PTX only)
// ---------------------------------------------------------------------------
__device__ __forceinline__ u64 pack2(float x, float y) {
    u64 r; asm("mov.b64 %0, {%1, %2};" : "=l"(r) : "f"(x), "f"(y)); return r;
}
__device__ __forceinline__ u64 dup2(float x) { return pack2(x, x); }
__device__ __forceinline__ void unpack2(u64 v, float& x, float& y) {
    asm("mov.b64 {%0, %1}, %2;" : "=f"(x), "=f"(y) : "l"(v));
}
__device__ __forceinline__ u64 ffma2(u64 a, u64 b, u64 c) {
    u64 d; asm("fma.rn.f32x2 %0, %1, %2, %3;" : "=l"(d) : "l"(a), "l"(b), "l"(c)); return d;
}
__device__ __forceinline__ u64 fadd2(u64 a, u64 b) {
    u64 d; asm("add.rn.f32x2 %0, %1, %2;" : "=l"(d) : "l"(a), "l"(b)); return d;
}
__device__ __forceinline__ u64 fmul2(u64 a, u64 b) {
    u64 d; asm("mul.rn.f32x2 %0, %1, %2;" : "=l"(d) : "l"(a), "l"(b)); return d;
}

__device__ __forceinline__ float sigmoidf_(float x) {
    return 1.0f / (1.0f + __expf(-x));
}

// ---------------------------------------------------------------------------
// Scratch (device globals — no allocations allowed)
// ---------------------------------------------------------------------------
__device__ float g_xproj_f[N_ROWS * G4];     // 16.8 MB
__device__ float g_xproj_r[N_ROWS * G4];     // 16.8 MB
__device__ float g_values [N_ROWS * HID];    //  8.4 MB
__device__ float g_hidden [N_ROWS * HID];    //  8.4 MB
__device__ float g_params [N_ROWS * NT * 8]; //  1.0 MB  (rd0..2, wd0..2, rw0, rw1)
__device__ float g_readout[N_ROWS * HID];    //  8.4 MB

// ---------------------------------------------------------------------------
// Kernel 1/5: C[M,N] = A[M,128] * B[N,128]^T + bias1[N] (+ bias2[N])
// BM=128, BN=64, BK=32, 256 threads, 8x4 microtile with row-paired f32x2 accs.
// ---------------------------------------------------------------------------
__global__ __launch_bounds__(256) void gemm_k128(
    const float* __restrict__ A, const float* __restrict__ B,
    const float* __restrict__ b1, const float* __restrict__ b2,
    float* __restrict__ C, int N)
{
    __shared__ __align__(16) float As[32][130];   // [k][row], pad keeps 8B align + few conflicts
    __shared__ __align__(16) float Bs[32][65];    // [k][col], conflict-free transpose store

    int tid = threadIdx.x;
    int tx = tid & 15;          // col group (4 cols)
    int ty = tid >> 4;          // row group (8 rows)
    int row0 = blockIdx.y * 128;
    int col0 = blockIdx.x * 64;

    const float4* A4 = (const float4*)A;
    const float4* B4 = (const float4*)B;

    u64 acc[4][4];
#pragma unroll
    for (int i = 0; i < 4; i++)
#pragma unroll
        for (int j = 0; j < 4; j++) acc[i][j] = 0ull;

#pragma unroll
    for (int kt = 0; kt < 4; kt++) {
        // load A tile 128x32 (transposed into As[k][r])
#pragma unroll
        for (int rep = 0; rep < 4; rep++) {
            int e = tid + 256 * rep;
            int r = e >> 3, k4 = e & 7;
            float4 v = A4[(row0 + r) * 32 + kt * 8 + k4];
            As[k4 * 4 + 0][r] = v.x; As[k4 * 4 + 1][r] = v.y;
            As[k4 * 4 + 2][r] = v.z; As[k4 * 4 + 3][r] = v.w;
        }
        // load B tile 64x32
#pragma unroll
        for (int rep = 0; rep < 2; rep++) {
            int e = tid + 256 * rep;
            int r = e >> 3, k4 = e & 7;
            float4 v = B4[(col0 + r) * 32 + kt * 8 + k4];
            Bs[k4 * 4 + 0][r] = v.x; Bs[k4 * 4 + 1][r] = v.y;
            Bs[k4 * 4 + 2][r] = v.z; Bs[k4 * 4 + 3][r] = v.w;
        }
        __syncthreads();

#pragma unroll
        for (int kk = 0; kk < 32; kk++) {
            u64 a2[4];
#pragma unroll
            for (int ip = 0; ip < 4; ip++)
                a2[ip] = *(const u64*)&As[kk][ty * 8 + 2 * ip];
#pragma unroll
            for (int j = 0; j < 4; j++) {
                u64 bd = dup2(Bs[kk][tx * 4 + j]);
#pragma unroll
                for (int ip = 0; ip < 4; ip++)
                    acc[ip][j] = ffma2(a2[ip], bd, acc[ip][j]);
            }
        }
        __syncthreads();
    }

#pragma unroll
    for (int j = 0; j < 4; j++) {
        int col = col0 + tx * 4 + j;
        float bv = b1[col] + (b2 ? b2[col] : 0.0f);
#pragma unroll
        for (int ip = 0; ip < 4; ip++) {
            float x, y; unpack2(acc[ip][j], x, y);
            int row = row0 + ty * 8 + 2 * ip;
            C[(size_t)row * N + col]       = x + bv;
            C[(size_t)(row + 1) * N + col] = y + bv;
        }
    }
}

// ---------------------------------------------------------------------------
// Kernel 2: bidirectional LSTM recurrence. One block per (batch, direction).
// Thread j owns gate j (W_hh row j resident in 32 f32x2 registers).
// ---------------------------------------------------------------------------
__global__ __launch_bounds__(256) void lstm_k(
    const float* __restrict__ xpf, const float* __restrict__ xpr,
    const float* __restrict__ Whh_f, const float* __restrict__ Whh_r,
    float* __restrict__ hidden)
{
    int b   = blockIdx.x & 63;
    int dir = blockIdx.x >> 6;
    int j   = threadIdx.x;

    const float* Whh = dir ? Whh_r : Whh_f;
    const float* xp  = dir ? xpr   : xpf;

    u64 w2[32];
    const u64* wrow = (const u64*)(Whh + j * 64);
#pragma unroll
    for (int k = 0; k < 32; k++) w2[k] = wrow[k];

    __shared__ __align__(16) float h_sm[64];
    __shared__ float act[256];
    if (j < 64) h_sm[j] = 0.0f;
    float c = 0.0f;
    __syncthreads();

    const u64* h2 = (const u64*)h_sm;

    for (int ss = 0; ss < S_LEN; ss++) {
        int s = dir ? (S_LEN - 1 - ss) : ss;
        float g = xp[(s * BSZ + b) * G4 + j];   // already includes b_ih + b_hh

        u64 a0 = 0ull, a1 = 0ull, a2 = 0ull, a3 = 0ull;
#pragma unroll
        for (int k = 0; k < 32; k += 4) {
            a0 = ffma2(w2[k + 0], h2[k + 0], a0);
            a1 = ffma2(w2[k + 1], h2[k + 1], a1);
            a2 = ffma2(w2[k + 2], h2[k + 2], a2);
            a3 = ffma2(w2[k + 3], h2[k + 3], a3);
        }
        u64 at = fadd2(fadd2(a0, a1), fadd2(a2, a3));
        float sx, sy; unpack2(at, sx, sy);
        g += sx + sy;

        float av = (j >= 128 && j < 192) ? tanhf(g) : sigmoidf_(g);
        act[j] = av;
        __syncthreads();

        if (j < 64) {
            c = act[64 + j] * c + act[j] * act[128 + j];
            float h = act[192 + j] * tanhf(c);
            h_sm[j] = h;
            hidden[(s * BSZ + b) * HID + dir * 64 + j] = h;
        }
        __syncthreads();
    }
}

// ---------------------------------------------------------------------------
// Kernel 3: action head + nonlinearities. One thread per (row, tape).
// params[row][t][8] = {rd0,rd1,rd2, wd0,wd1,wd2, rw_read, rw_write}
// ---------------------------------------------------------------------------
__global__ __launch_bounds__(256) void act_k(
    const float* __restrict__ hidden, const float* __restrict__ Wact,
    const float* __restrict__ bact, float* __restrict__ params)
{
    int gt  = blockIdx.x * 256 + threadIdx.x;   // 0 .. 32767
    int row = gt >> 1;
    int t   = gt & 1;

    const float4* h4 = (const float4*)(hidden + (size_t)row * HID);
    const float4* w4 = (const float4*)Wact;

    float acc[8];
#pragma unroll
    for (int jj = 0; jj < 8; jj++) acc[jj] = 0.0f;

#pragma unroll 4
    for (int k4 = 0; k4 < 32; k4++) {
        float4 h = __ldg(&h4[k4]);
#pragma unroll
        for (int jj = 0; jj < 8; jj++) {
            float4 w = __ldg(&w4[(t * 8 + jj) * 32 + k4]);
            acc[jj] += h.x * w.x + h.y * w.y + h.z * w.z + h.w * w.w;
        }
    }
#pragma unroll
    for (int jj = 0; jj < 8; jj++) acc[jj] += bact[t * 8 + jj];

    float out[8];
    // softmax over read dirs
    float m = fmaxf(acc[0], fmaxf(acc[1], acc[2]));
    float e0 = __expf(acc[0] - m), e1 = __expf(acc[1] - m), e2 = __expf(acc[2] - m);
    float inv = 1.0f / (e0 + e1 + e2);
    out[0] = e0 * inv; out[1] = e1 * inv; out[2] = e2 * inv;
    // softmax over write dirs
    m = fmaxf(acc[3], fmaxf(acc[4], acc[5]));
    e0 = __expf(acc[3] - m); e1 = __expf(acc[4] - m); e2 = __expf(acc[5] - m);
    inv = 1.0f / (e0 + e1 + e2);
    out[3] = e0 * inv; out[4] = e1 * inv; out[5] = e2 * inv;
    out[6] = sigmoidf_(acc[6]);
    out[7] = sigmoidf_(acc[7]);

    float4* p4 = (float4*)(params + (size_t)gt * 8);
    p4[0] = make_float4(out[0], out[1], out[2], out[3]);
    p4[1] = make_float4(out[4], out[5], out[6], out[7]);
}

// ---------------------------------------------------------------------------
// Kernel 4: tape scan. One block per (batch, tape) = 128 blocks, 256 threads.
// Tape [128 x 64] lives in smem as f32x2 column pairs. Positions kept
// pre-duplicated ((p,p) f32x2) so hot loops need zero pack instructions.
//   ow[c]  = sum_l tape[l,c] * wpos[l]
//   or_[c] = sum_l tape[l,c] * rpos[l]
//   sw     = sum_l wpos[l] * rpos[l]
//   delta  = (val - ow) * rw_write
//   tape  += wpos (x) delta
//   read   = (or_ + sw * delta) * rw_read          (== post-write read)
//   wpos'  = rpos[l+1]*wd0 + wpos[l]*wd1 + rpos[l-1]*wd2   (faithful to ref)
//   rpos'  = rpos[l+1]*rd0 + rpos[l]*rd1 + rpos[l-1]*rd2
// ---------------------------------------------------------------------------
__global__ __launch_bounds__(256) void tape_k(
    const float* __restrict__ values, const float* __restrict__ params,
    float* __restrict__ readouts,
    float* __restrict__ out_tape, float* __restrict__ out_rpos,
    float* __restrict__ out_wpos)
{
    int bt = blockIdx.x;        // b*2 + t
    int b  = bt >> 1;
    int t  = bt & 1;
    int tid = threadIdx.x;
    int q   = tid >> 5;         // 8 l-groups of 16
    int c2  = tid & 31;         // column pair

    __shared__ u64 tape2[TAPELEN][32];   // 32 KB
    __shared__ u64 wdup[TAPELEN], rdup[TAPELEN];
    __shared__ u64 pow_[8][32], por_[8][32];
    __shared__ u64 delta2[32];
    __shared__ float swp[4];
    __shared__ float ps[8];

    int l0 = q * 16;
#pragma unroll
    for (int i = 0; i < 16; i++) tape2[l0 + i][c2] = 0ull;
    if (tid < TAPELEN) {
        float v = (tid == 0) ? 1.0f : 0.0f;
        wdup[tid] = dup2(v);
        rdup[tid] = dup2(v);
    }
    __syncthreads();

    for (int s = 0; s < S_LEN; s++) {
        int sb = s * BSZ + b;
        if (tid < 8) ps[tid] = params[((size_t)sb * 2 + t) * 8 + tid];
        u64 val2 = 0ull;
        if (tid < 32)
            val2 = *(const u64*)(values + (size_t)sb * HID + t * 64 + 2 * c2);

        // --- two dot products in one tape sweep ---
        u64 owp = 0ull, orp = 0ull;
#pragma unroll
        for (int i = 0; i < 16; i++) {
            u64 tp = tape2[l0 + i][c2];
            owp = ffma2(tp, wdup[l0 + i], owp);
            orp = ffma2(tp, rdup[l0 + i], orp);
        }
        pow_[q][c2] = owp;
        por_[q][c2] = orp;

        float swpart = 0.0f;
        if (tid < TAPELEN) {
            float wx, d0, rx, d1;
            unpack2(wdup[tid], wx, d0);
            unpack2(rdup[tid], rx, d1);
            swpart = wx * rx;
        }
#pragma unroll
        for (int off = 16; off; off >>= 1)
            swpart += __shfl_down_sync(0xffffffffu, swpart, off);
        if (tid < TAPELEN && (tid & 31) == 0) swp[tid >> 5] = swpart;
        __syncthreads();

        float nw = 0.0f, nr = 0.0f;
        if (tid >= 128) {
            int l = tid - 128;
            float rd0 = ps[0], rd1 = ps[1], rd2 = ps[2];
            float wd0 = ps[3], wd1 = ps[4], wd2 = ps[5];
            float rl, rp1, rm1, wl, d_;
            unpack2(rdup[l], rl, d_);
            unpack2(rdup[(l + 1) & 127], rp1, d_);
            unpack2(rdup[(l - 1) & 127], rm1, d_);
            unpack2(wdup[l], wl, d_);
            nw = rp1 * wd0 + wl * wd1 + rm1 * wd2;
            nr = rp1 * rd0 + rl * rd1 + rm1 * rd2;
        } else if (tid < 32) {
            u64 ow2 = pow_[0][c2];
            u64 or2 = por_[0][c2];
#pragma unroll
            for (int qq = 1; qq < 8; qq++) {
                ow2 = fadd2(ow2, pow_[qq][c2]);
                or2 = fadd2(or2, por_[qq][c2]);
            }
            float sw = swp[0] + swp[1] + swp[2] + swp[3];
            float rw0 = ps[6], rw1 = ps[7];
            u64 d2 = fmul2(ffma2(ow2, dup2(-1.0f), val2), dup2(rw1));
            delta2[c2] = d2;
            u64 ro2 = fmul2(ffma2(d2, dup2(sw), or2), dup2(rw0));
            float rox, roy; unpack2(ro2, rox, roy);
            float2* ro = (float2*)(readouts + (size_t)sb * HID + t * 64 + 2 * c2);
            *ro = make_float2(rox, roy);
        }
        __syncthreads();

        // --- rank-1 tape update ---
        u64 d2 = delta2[c2];
#pragma unroll
        for (int i = 0; i < 16; i++)
            tape2[l0 + i][c2] = ffma2(wdup[l0 + i], d2, tape2[l0 + i][c2]);
        __syncthreads();

        if (tid >= 128) {
            int l = tid - 128;
            wdup[l] = dup2(nw);
            rdup[l] = dup2(nr);
        }
        __syncthreads();
    }

    // final state -> d_out
    if (out_tape) {
#pragma unroll
        for (int i = 0; i < 16; i++) {
            int l = l0 + i;
            float x, y; unpack2(tape2[l][c2], x, y);
            float2* dst = (float2*)(out_tape + ((size_t)(l * BSZ + b) * 2 + t) * 64 + 2 * c2);
            *dst = make_float2(x, y);
        }
        if (tid < TAPELEN) {
            float rx, wx, d_;
            unpack2(rdup[tid], rx, d_);
            unpack2(wdup[tid], wx, d_);
            out_rpos[(size_t)(tid * BSZ + b) * 2 + t] = rx;
            out_wpos[(size_t)(tid * BSZ + b) * 2 + t] = wx;
        }
    }
}

// ---------------------------------------------------------------------------
// Launcher
// ---------------------------------------------------------------------------
extern "C" void kernel_launch(void* const* d_in, const int* in_sizes, int n_in,
                              void* d_out, int out_size)
{
    const float* inputs = (const float*)d_in[0];
    // d_in[1] = tapelen (int32, fixed 128 — hardcoded)
    const float* W_ih_f = (const float*)d_in[2];
    const float* W_hh_f = (const float*)d_in[3];
    const float* b_ih_f = (const float*)d_in[4];
    const float* b_hh_f = (const float*)d_in[5];
    const float* W_ih_r = (const float*)d_in[6];
    const float* W_hh_r = (const float*)d_in[7];
    const float* b_ih_r = (const float*)d_in[8];
    const float* b_hh_r = (const float*)d_in[9];
    const float* W_act  = (const float*)d_in[10];
    const float* b_act  = (const float*)d_in[11];
    const float* W_val  = (const float*)d_in[12];
    const float* b_val  = (const float*)d_in[13];
    const float* W_out  = (const float*)d_in[14];
    const float* b_out  = (const float*)d_in[15];

    float* out = (float*)d_out;

    float *xf, *xr, *vals, *hid, *prm, *ro;
    cudaGetSymbolAddress((void**)&xf,   g_xproj_f);
    cudaGetSymbolAddress((void**)&xr,   g_xproj_r);
    cudaGetSymbolAddress((void**)&vals, g_values);
    cudaGetSymbolAddress((void**)&hid,  g_hidden);
    cudaGetSymbolAddress((void**)&prm,  g_params);
    cudaGetSymbolAddress((void**)&ro,   g_readout);

    // Phase 1: input projections (independent GEMMs, K=128)
    gemm_k128<<<dim3(G4 / 64, N_ROWS / 128), 256>>>(inputs, W_ih_f, b_ih_f, b_hh_f, xf, G4);
    gemm_k128<<<dim3(G4 / 64, N_ROWS / 128), 256>>>(inputs, W_ih_r, b_ih_r, b_hh_r, xr, G4);
    gemm_k128<<<dim3(HID / 64, N_ROWS / 128), 256>>>(inputs, W_val, b_val, nullptr, vals, HID);

    // Phase 2: LSTM recurrence (128 blocks: batch x direction)
    lstm_k<<<128, 256>>>(xf, xr, W_hh_f, W_hh_r, hid);

    // Phase 3: action head
    act_k<<<128, 256>>>(hid, W_act, b_act, prm);

    // Phase 4: tape scan (128 blocks: batch x tape)
    bool full_out = (out_size >= OUT_TOTAL);
    tape_k<<<128, 256>>>(vals, prm, ro,
                         full_out ? out + OUT_TAPE_OFF : nullptr,
                         full_out ? out + OUT_RPOS_OFF : nullptr,
                         full_out ? out + OUT_WPOS_OFF : nullptr);

    // Phase 5: output projection straight into d_out
    gemm_k128<<<dim3(HID / 64, N_ROWS / 128), 256>>>(ro, W_out, b_out, nullptr, out, HID);
}

// round 2
// speedup vs baseline: 1.0090x; 1.0090x over previous
#include <cuda_runtime.h>
#include <cuda_bf16.h>

// ---------------------------------------------------------------------------
// Problem constants (fixed by the dataset)
// ---------------------------------------------------------------------------
#define S_LEN   256
#define BSZ     64
#define IN_DIM  128
#define HID     128
#define NT      2
#define TAPELEN 128
#define DIM     64          // HID / NT
#define LH      64          // HID / 2
#define G4      256         // 4 * LH

#define N_ROWS  (S_LEN * BSZ)          // 16384

// d_out layout: outputs [S,B,HID], tape [TL,B,NT,DIM], rpos [TL,B,NT], wpos [TL,B,NT]
#define OUT_OUTPUTS_SZ  (S_LEN * BSZ * HID)                 // 2097152
#define OUT_TAPE_OFF    (OUT_OUTPUTS_SZ)
#define OUT_TAPE_SZ     (TAPELEN * BSZ * NT * DIM)          // 1048576
#define OUT_RPOS_OFF    (OUT_TAPE_OFF + OUT_TAPE_SZ)
#define OUT_POS_SZ      (TAPELEN * BSZ * NT)                // 16384
#define OUT_WPOS_OFF    (OUT_RPOS_OFF + OUT_POS_SZ)
#define OUT_TOTAL       (OUT_WPOS_OFF + OUT_POS_SZ)

typedef unsigned long long u64;

// ---------------------------------------------------------------------------
// f32x2 packed-math helpers (Blackwell FFMA2 path — PTX only)
// ---------------------------------------------------------------------------
__device__ __forceinline__ u64 pack2(float x, float y) {
    u64 r; asm("mov.b64 %0, {%1, %2};" : "=l"(r) : "f"(x), "f"(y)); return r;
}
__device__ __forceinline__ u64 dup2(float x) { return pack2(x, x); }
__device__ __forceinline__ void unpack2(u64 v, float& x, float& y) {
    asm("mov.b64 {%0, %1}, %2;" : "=f"(x), "=f"(y) : "l"(v));
}
__device__ __forceinline__ u64 ffma2(u64 a, u64 b, u64 c) {
    u64 d; asm("fma.rn.f32x2 %0, %1, %2, %3;" : "=l"(d) : "l"(a), "l"(b), "l"(c)); return d;
}
__device__ __forceinline__ u64 fadd2(u64 a, u64 b) {
    u64 d; asm("add.rn.f32x2 %0, %1, %2;" : "=l"(d) : "l"(a), "l"(b)); return d;
}
__device__ __forceinline__ u64 fmul2(u64 a, u64 b) {
    u64 d; asm("mul.rn.f32x2 %0, %1, %2;" : "=l"(d) : "l"(a), "l"(b)); return d;
}

__device__ __forceinline__ float sigmoidf_(float x) {
    return 1.0f / (1.0f + __expf(-x));
}
// tanh(x) = 2*sigmoid(2x) - 1  — MUFU-based, NaN-free at +/- inf
__device__ __forceinline__ float tanh_fast(float x) {
    return 2.0f / (1.0f + __expf(-2.0f * x)) - 1.0f;
}

// ---------------------------------------------------------------------------
// Scratch (device globals — no allocations allowed)
// ---------------------------------------------------------------------------
__device__ float g_xproj_f[N_ROWS * G4];     // 16.8 MB
__device__ float g_xproj_r[N_ROWS * G4];     // 16.8 MB
__device__ float g_values [N_ROWS * HID];    //  8.4 MB
__device__ float g_hidden [N_ROWS * HID];    //  8.4 MB
__device__ float g_params [N_ROWS * NT * 8]; //  1.0 MB
__device__ float g_readout[N_ROWS * HID];    //  8.4 MB

// ---------------------------------------------------------------------------
// GEMM core: C[M,N] = A[M,128] * B[N,128]^T + bias1[N] (+ bias2[N])
// BM=128, BN=64, BK=32, 256 threads, 8x4 microtile with row-paired f32x2 accs.
// ---------------------------------------------------------------------------
__device__ __forceinline__ void gemm_tile(
    const float* __restrict__ A, const float* __restrict__ B,
    const float* __restrict__ b1, const float* __restrict__ b2,
    float* __restrict__ C, int N, int row0, int col0)
{
    __shared__ __align__(16) float As[32][130];
    __shared__ __align__(16) float Bs[32][65];

    int tid = threadIdx.x;
    int tx = tid & 15;          // col group (4 cols)
    int ty = tid >> 4;          // row group (8 rows)

    const float4* A4 = (const float4*)A;
    const float4* B4 = (const float4*)B;

    u64 acc[4][4];
#pragma unroll
    for (int i = 0; i < 4; i++)
#pragma unroll
        for (int j = 0; j < 4; j++) acc[i][j] = 0ull;

#pragma unroll
    for (int kt = 0; kt < 4; kt++) {
#pragma unroll
        for (int rep = 0; rep < 4; rep++) {
            int e = tid + 256 * rep;
            int r = e >> 3, k4 = e & 7;
            float4 v = A4[(size_t)(row0 + r) * 32 + kt * 8 + k4];
            As[k4 * 4 + 0][r] = v.x; As[k4 * 4 + 1][r] = v.y;
            As[k4 * 4 + 2][r] = v.z; As[k4 * 4 + 3][r] = v.w;
        }
#pragma unroll
        for (int rep = 0; rep < 2; rep++) {
            int e = tid + 256 * rep;
            int r = e >> 3, k4 = e & 7;
            float4 v = B4[(size_t)(col0 + r) * 32 + kt * 8 + k4];
            Bs[k4 * 4 + 0][r] = v.x; Bs[k4 * 4 + 1][r] = v.y;
            Bs[k4 * 4 + 2][r] = v.z; Bs[k4 * 4 + 3][r] = v.w;
        }
        __syncthreads();

#pragma unroll
        for (int kk = 0; kk < 32; kk++) {
            u64 a2[4];
#pragma unroll
            for (int ip = 0; ip < 4; ip++)
                a2[ip] = *(const u64*)&As[kk][ty * 8 + 2 * ip];
#pragma unroll
            for (int j = 0; j < 4; j++) {
                u64 bd = dup2(Bs[kk][tx * 4 + j]);
#pragma unroll
                for (int ip = 0; ip < 4; ip++)
                    acc[ip][j] = ffma2(a2[ip], bd, acc[ip][j]);
            }
        }
        __syncthreads();
    }

#pragma unroll
    for (int j = 0; j < 4; j++) {
        int col = col0 + tx * 4 + j;
        float bv = b1[col] + (b2 ? b2[col] : 0.0f);
#pragma unroll
        for (int ip = 0; ip < 4; ip++) {
            float x, y; unpack2(acc[ip][j], x, y);
            int row = row0 + ty * 8 + 2 * ip;
            C[(size_t)row * N + col]       = x + bv;
            C[(size_t)(row + 1) * N + col] = y + bv;
        }
    }
}

// Fused input projections: 3 GEMMs (f-gates 256 cols, r-gates 256 cols, values 128 cols)
__global__ __launch_bounds__(256) void gemm_fused_in(
    const float* __restrict__ A,
    const float* __restrict__ Wf, const float* __restrict__ bf1, const float* __restrict__ bf2,
    const float* __restrict__ Wr, const float* __restrict__ br1, const float* __restrict__ br2,
    const float* __restrict__ Wv, const float* __restrict__ bv1,
    float* __restrict__ Cf, float* __restrict__ Cr, float* __restrict__ Cv)
{
    int cb = blockIdx.x;            // 0..9
    int row0 = blockIdx.y * 128;
    if (cb < 4)      gemm_tile(A, Wf, bf1, bf2,     Cf, G4,  row0, cb * 64);
    else if (cb < 8) gemm_tile(A, Wr, br1, br2,     Cr, G4,  row0, (cb - 4) * 64);
    else             gemm_tile(A, Wv, bv1, nullptr, Cv, HID, row0, (cb - 8) * 64);
}

__global__ __launch_bounds__(256) void gemm_k128(
    const float* __restrict__ A, const float* __restrict__ B,
    const float* __restrict__ b1, float* __restrict__ C, int N)
{
    gemm_tile(A, B, b1, nullptr, C, N, blockIdx.y * 128, blockIdx.x * 64);
}

// ---------------------------------------------------------------------------
// Kernel 2: bidirectional LSTM recurrence. One block per (batch, direction).
// Thread j owns gate j (W_hh row j resident in 32 f32x2 registers).
// xp pre-activation for step s+1 is prefetched during step s.
// ---------------------------------------------------------------------------
__global__ __launch_bounds__(256) void lstm_k(
    const float* __restrict__ xpf, const float* __restrict__ xpr,
    const float* __restrict__ Whh_f, const float* __restrict__ Whh_r,
    float* __restrict__ hidden)
{
    int b   = blockIdx.x & 63;
    int dir = blockIdx.x >> 6;
    int j   = threadIdx.x;

    const float* Whh = dir ? Whh_r : Whh_f;
    const float* xp  = dir ? xpr   : xpf;

    u64 w2[32];
    const u64* wrow = (const u64*)(Whh + j * 64);
#pragma unroll
    for (int k = 0; k < 32; k++) w2[k] = wrow[k];

    __shared__ __align__(16) float h_sm[64];
    __shared__ float act[256];
    if (j < 64) h_sm[j] = 0.0f;
    float c = 0.0f;
    __syncthreads();

    const u64* h2 = (const u64*)h_sm;
    const float* xbase = xp + (size_t)b * G4 + j;

    int s   = dir ? (S_LEN - 1) : 0;
    int stp = dir ? -1 : 1;
    float gn = __ldg(&xbase[(size_t)s * (BSZ * G4)]);   // prefetch step 0

    for (int ss = 0; ss < S_LEN; ss++) {
        float g = gn;
        int s_cur = s;
        s += stp;
        if (ss + 1 < S_LEN)
            gn = __ldg(&xbase[(size_t)s * (BSZ * G4)]);  // prefetch next step

        u64 a0 = 0ull, a1 = 0ull, a2 = 0ull, a3 = 0ull;
#pragma unroll
        for (int k = 0; k < 32; k += 4) {
            a0 = ffma2(w2[k + 0], h2[k + 0], a0);
            a1 = ffma2(w2[k + 1], h2[k + 1], a1);
            a2 = ffma2(w2[k + 2], h2[k + 2], a2);
            a3 = ffma2(w2[k + 3], h2[k + 3], a3);
        }
        u64 at = fadd2(fadd2(a0, a1), fadd2(a2, a3));
        float sx, sy; unpack2(at, sx, sy);
        g += sx + sy;

        float av = (j >= 128 && j < 192) ? tanh_fast(g) : sigmoidf_(g);
        act[j] = av;
        __syncthreads();

        if (j < 64) {
            c = act[64 + j] * c + act[j] * act[128 + j];
            float h = act[192 + j] * tanh_fast(c);
            h_sm[j] = h;
            hidden[(size_t)(s_cur * BSZ + b) * HID + dir * 64 + j] = h;
        }
        __syncthreads();
    }
}

// ---------------------------------------------------------------------------
// Kernel 3: action head + nonlinearities. One thread per (row, tape).
// params[row][t][8] = {rd0,rd1,rd2, wd0,wd1,wd2, rw_read, rw_write}
// ---------------------------------------------------------------------------
__global__ __launch_bounds__(256) void act_k(
    const float* __restrict__ hidden, const float* __restrict__ Wact,
    const float* __restrict__ bact, float* __restrict__ params)
{
    int gt  = blockIdx.x * 256 + threadIdx.x;   // 0 .. 32767
    int row = gt >> 1;
    int t   = gt & 1;

    const float4* h4 = (const float4*)(hidden + (size_t)row * HID);
    const float4* w4 = (const float4*)Wact;

    float acc[8];
#pragma unroll
    for (int jj = 0; jj < 8; jj++) acc[jj] = 0.0f;

#pragma unroll 4
    for (int k4 = 0; k4 < 32; k4++) {
        float4 h = __ldg(&h4[k4]);
#pragma unroll
        for (int jj = 0; jj < 8; jj++) {
            float4 w = __ldg(&w4[(t * 8 + jj) * 32 + k4]);
            acc[jj] += h.x * w.x + h.y * w.y + h.z * w.z + h.w * w.w;
        }
    }
#pragma unroll
    for (int jj = 0; jj < 8; jj++) acc[jj] += bact[t * 8 + jj];

    float out[8];
    float m = fmaxf(acc[0], fmaxf(acc[1], acc[2]));
    float e0 = __expf(acc[0] - m), e1 = __expf(acc[1] - m), e2 = __expf(acc[2] - m);
    float inv = 1.0f / (e0 + e1 + e2);
    out[0] = e0 * inv; out[1] = e1 * inv; out[2] = e2 * inv;
    m = fmaxf(acc[3], fmaxf(acc[4], acc[5]));
    e0 = __expf(acc[3] - m); e1 = __expf(acc[4] - m); e2 = __expf(acc[5] - m);
    inv = 1.0f / (e0 + e1 + e2);
    out[3] = e0 * inv; out[4] = e1 * inv; out[5] = e2 * inv;
    out[6] = sigmoidf_(acc[6]);
    out[7] = sigmoidf_(acc[7]);

    float4* p4 = (float4*)(params + (size_t)gt * 8);
    p4[0] = make_float4(out[0], out[1], out[2], out[3]);
    p4[1] = make_float4(out[4], out[5], out[6], out[7]);
}

// ---------------------------------------------------------------------------
// Kernel 4: tape scan. One block per (batch, tape) = 128 blocks, 256 threads.
// 3 barriers/step (double-buffered positions), params/values prefetched.
// ---------------------------------------------------------------------------
__global__ __launch_bounds__(256) void tape_k(
    const float* __restrict__ values, const float* __restrict__ params,
    float* __restrict__ readouts,
    float* __restrict__ out_tape, float* __restrict__ out_rpos,
    float* __restrict__ out_wpos)
{
    int bt = blockIdx.x;        // b*2 + t
    int b  = bt >> 1;
    int t  = bt & 1;
    int tid = threadIdx.x;
    int q   = tid >> 5;         // 8 l-groups of 16
    int c2  = tid & 31;         // column pair

    __shared__ u64 tape2[TAPELEN][32];        // 32 KB
    __shared__ u64 wdup[2][TAPELEN], rdup[2][TAPELEN];
    __shared__ u64 pow_[8][32], por_[8][32];
    __shared__ u64 delta2[32];
    __shared__ float swp[4];

    int l0 = q * 16;
#pragma unroll
    for (int i = 0; i < 16; i++) tape2[l0 + i][c2] = 0ull;
    if (tid < TAPELEN) {
        float v = (tid == 0) ? 1.0f : 0.0f;
        wdup[0][tid] = dup2(v);
        rdup[0][tid] = dup2(v);
    }

    // prefetch step 0
    const float4* pbase = (const float4*)(params + ((size_t)b * 2 + t) * 8);
    float4 pp0 = __ldg(&pbase[0]);
    float4 pp1 = __ldg(&pbase[1]);
    u64 val2 = 0ull;
    if (tid < 32)
        val2 = __ldg((const u64*)(values + (size_t)b * HID + t * 64 + 2 * c2));
    __syncthreads();

    int cur = 0;
    for (int s = 0; s < S_LEN; s++) {
        int nxt = cur ^ 1;
        int sb  = s * BSZ + b;

        // --- stage A: two dot products in one tape sweep + sw partial ---
        u64 owp = 0ull, orp = 0ull;
#pragma unroll
        for (int i = 0; i < 16; i++) {
            u64 tp = tape2[l0 + i][c2];
            owp = ffma2(tp, wdup[cur][l0 + i], owp);
            orp = ffma2(tp, rdup[cur][l0 + i], orp);
        }
        pow_[q][c2] = owp;
        por_[q][c2] = orp;

        float swpart = 0.0f;
        if (tid < TAPELEN) {
            float wx, d0, rx, d1;
            unpack2(wdup[cur][tid], wx, d0);
            unpack2(rdup[cur][tid], rx, d1);
            swpart = wx * rx;
        }
#pragma unroll
        for (int off = 16; off; off >>= 1)
            swpart += __shfl_down_sync(0xffffffffu, swpart, off);
        if (tid < TAPELEN && (tid & 31) == 0) swp[tid >> 5] = swpart;
        __syncthreads();

        // --- stage B: delta/readout (warp 0) and new positions (warps 4-7) ---
        float nw = 0.0f, nr = 0.0f;
        if (tid >= 128) {
            int l = tid - 128;
            float rd0 = pp0.x, rd1 = pp0.y, rd2 = pp0.z;
            float wd0 = pp0.w, wd1 = pp1.x, wd2 = pp1.y;
            float rl, rp1, rm1, wl, d_;
            unpack2(rdup[cur][l], rl, d_);
            unpack2(rdup[cur][(l + 1) & 127], rp1, d_);
            unpack2(rdup[cur][(l - 1) & 127], rm1, d_);
            unpack2(wdup[cur][l], wl, d_);
            nw = rp1 * wd0 + wl * wd1 + rm1 * wd2;
            nr = rp1 * rd0 + rl * rd1 + rm1 * rd2;
        } else if (tid < 32) {
            u64 ow2 = pow_[0][c2];
            u64 or2 = por_[0][c2];
#pragma unroll
            for (int qq = 1; qq < 8; qq++) {
                ow2 = fadd2(ow2, pow_[qq][c2]);
                or2 = fadd2(or2, por_[qq][c2]);
            }
            float sw = swp[0] + swp[1] + swp[2] + swp[3];
            float rw0 = pp1.z, rw1 = pp1.w;
            u64 d2 = fmul2(ffma2(ow2, dup2(-1.0f), val2), dup2(rw1));
            delta2[c2] = d2;
            u64 ro2 = fmul2(ffma2(d2, dup2(sw), or2), dup2(rw0));
            float rox, roy; unpack2(ro2, rox, roy);
            float2* ro = (float2*)(readouts + (size_t)sb * HID + t * 64 + 2 * c2);
            *ro = make_float2(rox, roy);
        }
        __syncthreads();

        // --- stage C: rank-1 tape update + publish new positions + prefetch ---
        u64 d2 = delta2[c2];
#pragma unroll
        for (int i = 0; i < 16; i++)
            tape2[l0 + i][c2] = ffma2(wdup[cur][l0 + i], d2, tape2[l0 + i][c2]);

        if (tid >= 128) {
            int l = tid - 128;
            wdup[nxt][l] = dup2(nw);
            rdup[nxt][l] = dup2(nr);
        }

        if (s + 1 < S_LEN) {
            int sn = (s + 1) * BSZ + b;
            const float4* pb = (const float4*)(params + ((size_t)sn * 2 + t) * 8);
            pp0 = __ldg(&pb[0]);
            pp1 = __ldg(&pb[1]);
            if (tid < 32)
                val2 = __ldg((const u64*)(values + (size_t)sn * HID + t * 64 + 2 * c2));
        }
        __syncthreads();
        cur = nxt;
    }

    // final state -> d_out
    if (out_tape) {
#pragma unroll
        for (int i = 0; i < 16; i++) {
            int l = l0 + i;
            float x, y; unpack2(tape2[l][c2], x, y);
            float2* dst = (float2*)(out_tape + ((size_t)(l * BSZ + b) * 2 + t) * 64 + 2 * c2);
            *dst = make_float2(x, y);
        }
        if (tid < TAPELEN) {
            float rx, wx, d_;
            unpack2(rdup[cur][tid], rx, d_);
            unpack2(wdup[cur][tid], wx, d_);
            out_rpos[(size_t)(tid * BSZ + b) * 2 + t] = rx;
            out_wpos[(size_t)(tid * BSZ + b) * 2 + t] = wx;
        }
    }
}

// ---------------------------------------------------------------------------
// Launcher
// ---------------------------------------------------------------------------
extern "C" void kernel_launch(void* const* d_in, const int* in_sizes, int n_in,
                              void* d_out, int out_size)
{
    const float* inputs = (const float*)d_in[0];
    const float* W_ih_f = (const float*)d_in[2];
    const float* W_hh_f = (const float*)d_in[3];
    const float* b_ih_f = (const float*)d_in[4];
    const float* b_hh_f = (const float*)d_in[5];
    const float* W_ih_r = (const float*)d_in[6];
    const float* W_hh_r = (const float*)d_in[7];
    const float* b_ih_r = (const float*)d_in[8];
    const float* b_hh_r = (const float*)d_in[9];
    const float* W_act  = (const float*)d_in[10];
    const float* b_act  = (const float*)d_in[11];
    const float* W_val  = (const float*)d_in[12];
    const float* b_val  = (const float*)d_in[13];
    const float* W_out  = (const float*)d_in[14];
    const float* b_out  = (const float*)d_in[15];

    float* out = (float*)d_out;

    float *xf, *xr, *vals, *hid, *prm, *ro;
    cudaGetSymbolAddress((void**)&xf,   g_xproj_f);
    cudaGetSymbolAddress((void**)&xr,   g_xproj_r);
    cudaGetSymbolAddress((void**)&vals, g_values);
    cudaGetSymbolAddress((void**)&hid,  g_hidden);
    cudaGetSymbolAddress((void**)&prm,  g_params);
    cudaGetSymbolAddress((void**)&ro,   g_readout);

    // Phase 1: fused input projections (one launch, 1280 blocks)
    gemm_fused_in<<<dim3(10, N_ROWS / 128), 256>>>(
        inputs,
        W_ih_f, b_ih_f, b_hh_f,
        W_ih_r, b_ih_r, b_hh_r,
        W_val,  b_val,
        xf, xr, vals);

    // Phase 2: LSTM recurrence (128 blocks: batch x direction)
    lstm_k<<<128, 256>>>(xf, xr, W_hh_f, W_hh_r, hid);

    // Phase 3: action head
    act_k<<<128, 256>>>(hid, W_act, b_act, prm);

    // Phase 4: tape scan (128 blocks: batch x tape)
    bool full_out = (out_size >= OUT_TOTAL);
    tape_k<<<128, 256>>>(vals, prm, ro,
                         full_out ? out + OUT_TAPE_OFF : nullptr,
                         full_out ? out + OUT_RPOS_OFF : nullptr,
                         full_out ? out + OUT_WPOS_OFF : nullptr);

    // Phase 5: output projection straight into d_out
    gemm_k128<<<dim3(HID / 64, N_ROWS / 128), 256>>>(ro, W_out, b_out, out, HID);
}

// round 3
// speedup vs baseline: 1.4878x; 1.4746x over previous
#include <cuda_runtime.h>
#include <cuda_bf16.h>

// ---------------------------------------------------------------------------
// Problem constants (fixed by the dataset)
// ---------------------------------------------------------------------------
#define S_LEN   256
#define BSZ     64
#define IN_DIM  128
#define HID     128
#define NT      2
#define TAPELEN 128
#define DIM     64          // HID / NT
#define LH      64          // HID / 2
#define G4      256         // 4 * LH

#define N_ROWS  (S_LEN * BSZ)          // 16384

// d_out layout: outputs [S,B,HID], tape [TL,B,NT,DIM], rpos [TL,B,NT], wpos [TL,B,NT]
#define OUT_OUTPUTS_SZ  (S_LEN * BSZ * HID)                 // 2097152
#define OUT_TAPE_OFF    (OUT_OUTPUTS_SZ)
#define OUT_TAPE_SZ     (TAPELEN * BSZ * NT * DIM)          // 1048576
#define OUT_RPOS_OFF    (OUT_TAPE_OFF + OUT_TAPE_SZ)
#define OUT_POS_SZ      (TAPELEN * BSZ * NT)                // 16384
#define OUT_WPOS_OFF    (OUT_RPOS_OFF + OUT_POS_SZ)
#define OUT_TOTAL       (OUT_WPOS_OFF + OUT_POS_SZ)

typedef unsigned long long u64;

// ---------------------------------------------------------------------------
// f32x2 packed-math helpers (Blackwell FFMA2 path — PTX only)
// ---------------------------------------------------------------------------
__device__ __forceinline__ u64 pack2(float x, float y) {
    u64 r; asm("mov.b64 %0, {%1, %2};" : "=l"(r) : "f"(x), "f"(y)); return r;
}
__device__ __forceinline__ u64 dup2(float x) { return pack2(x, x); }
__device__ __forceinline__ void unpack2(u64 v, float& x, float& y) {
    asm("mov.b64 {%0, %1}, %2;" : "=f"(x), "=f"(y) : "l"(v));
}
__device__ __forceinline__ u64 ffma2(u64 a, u64 b, u64 c) {
    u64 d; asm("fma.rn.f32x2 %0, %1, %2, %3;" : "=l"(d) : "l"(a), "l"(b), "l"(c)); return d;
}
__device__ __forceinline__ u64 fadd2(u64 a, u64 b) {
    u64 d; asm("add.rn.f32x2 %0, %1, %2;" : "=l"(d) : "l"(a), "l"(b)); return d;
}
__device__ __forceinline__ u64 fmul2(u64 a, u64 b) {
    u64 d; asm("mul.rn.f32x2 %0, %1, %2;" : "=l"(d) : "l"(a), "l"(b)); return d;
}

__device__ __forceinline__ float sigmoidf_(float x) {
    return 1.0f / (1.0f + __expf(-x));
}
// tanh(x) = 2*sigmoid(2x) - 1  — MUFU-based, NaN-free at +/- inf
__device__ __forceinline__ float tanh_fast(float x) {
    return 2.0f / (1.0f + __expf(-2.0f * x)) - 1.0f;
}

// ---------------------------------------------------------------------------
// Scratch (device globals — no allocations allowed)
// ---------------------------------------------------------------------------
__device__ float g_xproj_f[N_ROWS * G4];     // 16.8 MB
__device__ float g_xproj_r[N_ROWS * G4];     // 16.8 MB
__device__ float g_values [N_ROWS * HID];    //  8.4 MB
__device__ float g_hidden [N_ROWS * HID];    //  8.4 MB
__device__ float g_params [N_ROWS * NT * 8]; //  1.0 MB
__device__ float g_readout[N_ROWS * HID];    //  8.4 MB

// ---------------------------------------------------------------------------
// GEMM core: C[M,N] = A[M,128] * B[N,128]^T + bias1[N] (+ bias2[N])
// BM=128, BN=64, BK=32, 256 threads, 8x4 microtile with row-paired f32x2 accs.
// ---------------------------------------------------------------------------
__device__ __forceinline__ void gemm_tile(
    const float* __restrict__ A, const float* __restrict__ B,
    const float* __restrict__ b1, const float* __restrict__ b2,
    float* __restrict__ C, int N, int row0, int col0)
{
    __shared__ __align__(16) float As[32][130];
    __shared__ __align__(16) float Bs[32][65];

    int tid = threadIdx.x;
    int tx = tid & 15;          // col group (4 cols)
    int ty = tid >> 4;          // row group (8 rows)

    const float4* A4 = (const float4*)A;
    const float4* B4 = (const float4*)B;

    u64 acc[4][4];
#pragma unroll
    for (int i = 0; i < 4; i++)
#pragma unroll
        for (int j = 0; j < 4; j++) acc[i][j] = 0ull;

#pragma unroll
    for (int kt = 0; kt < 4; kt++) {
#pragma unroll
        for (int rep = 0; rep < 4; rep++) {
            int e = tid + 256 * rep;
            int r = e >> 3, k4 = e & 7;
            float4 v = A4[(size_t)(row0 + r) * 32 + kt * 8 + k4];
            As[k4 * 4 + 0][r] = v.x; As[k4 * 4 + 1][r] = v.y;
            As[k4 * 4 + 2][r] = v.z; As[k4 * 4 + 3][r] = v.w;
        }
#pragma unroll
        for (int rep = 0; rep < 2; rep++) {
            int e = tid + 256 * rep;
            int r = e >> 3, k4 = e & 7;
            float4 v = B4[(size_t)(col0 + r) * 32 + kt * 8 + k4];
            Bs[k4 * 4 + 0][r] = v.x; Bs[k4 * 4 + 1][r] = v.y;
            Bs[k4 * 4 + 2][r] = v.z; Bs[k4 * 4 + 3][r] = v.w;
        }
        __syncthreads();

#pragma unroll
        for (int kk = 0; kk < 32; kk++) {
            u64 a2[4];
#pragma unroll
            for (int ip = 0; ip < 4; ip++)
                a2[ip] = *(const u64*)&As[kk][ty * 8 + 2 * ip];
#pragma unroll
            for (int j = 0; j < 4; j++) {
                u64 bd = dup2(Bs[kk][tx * 4 + j]);
#pragma unroll
                for (int ip = 0; ip < 4; ip++)
                    acc[ip][j] = ffma2(a2[ip], bd, acc[ip][j]);
            }
        }
        __syncthreads();
    }

#pragma unroll
    for (int j = 0; j < 4; j++) {
        int col = col0 + tx * 4 + j;
        float bv = b1[col] + (b2 ? b2[col] : 0.0f);
#pragma unroll
        for (int ip = 0; ip < 4; ip++) {
            float x, y; unpack2(acc[ip][j], x, y);
            int row = row0 + ty * 8 + 2 * ip;
            C[(size_t)row * N + col]       = x + bv;
            C[(size_t)(row + 1) * N + col] = y + bv;
        }
    }
}

// Fused input projections: 3 GEMMs (f-gates 256 cols, r-gates 256 cols, values 128 cols)
__global__ __launch_bounds__(256) void gemm_fused_in(
    const float* __restrict__ A,
    const float* __restrict__ Wf, const float* __restrict__ bf1, const float* __restrict__ bf2,
    const float* __restrict__ Wr, const float* __restrict__ br1, const float* __restrict__ br2,
    const float* __restrict__ Wv, const float* __restrict__ bv1,
    float* __restrict__ Cf, float* __restrict__ Cr, float* __restrict__ Cv)
{
    int cb = blockIdx.x;            // 0..9
    int row0 = blockIdx.y * 128;
    if (cb < 4)      gemm_tile(A, Wf, bf1, bf2,     Cf, G4,  row0, cb * 64);
    else if (cb < 8) gemm_tile(A, Wr, br1, br2,     Cr, G4,  row0, (cb - 4) * 64);
    else             gemm_tile(A, Wv, bv1, nullptr, Cv, HID, row0, (cb - 8) * 64);
}

__global__ __launch_bounds__(256) void gemm_k128(
    const float* __restrict__ A, const float* __restrict__ B,
    const float* __restrict__ b1, float* __restrict__ C, int N)
{
    gemm_tile(A, B, b1, nullptr, C, N, blockIdx.y * 128, blockIdx.x * 64);
}

// ---------------------------------------------------------------------------
// Kernel 2: bidirectional LSTM recurrence. One block per (batch, direction).
// Thread j owns gate j (W_hh row j resident in 32 f32x2 registers).
// xp pre-activation for step s+1 is prefetched during step s.
// ---------------------------------------------------------------------------
__global__ __launch_bounds__(256) void lstm_k(
    const float* __restrict__ xpf, const float* __restrict__ xpr,
    const float* __restrict__ Whh_f, const float* __restrict__ Whh_r,
    float* __restrict__ hidden)
{
    int b   = blockIdx.x & 63;
    int dir = blockIdx.x >> 6;
    int j   = threadIdx.x;

    const float* Whh = dir ? Whh_r : Whh_f;
    const float* xp  = dir ? xpr   : xpf;

    u64 w2[32];
    const u64* wrow = (const u64*)(Whh + j * 64);
#pragma unroll
    for (int k = 0; k < 32; k++) w2[k] = wrow[k];

    __shared__ __align__(16) float h_sm[64];
    __shared__ float act[256];
    if (j < 64) h_sm[j] = 0.0f;
    float c = 0.0f;
    __syncthreads();

    const u64* h2 = (const u64*)h_sm;
    const float* xbase = xp + (size_t)b * G4 + j;

    int s   = dir ? (S_LEN - 1) : 0;
    int stp = dir ? -1 : 1;
    float gn = __ldg(&xbase[(size_t)s * (BSZ * G4)]);   // prefetch step 0

    for (int ss = 0; ss < S_LEN; ss++) {
        float g = gn;
        int s_cur = s;
        s += stp;
        if (ss + 1 < S_LEN)
            gn = __ldg(&xbase[(size_t)s * (BSZ * G4)]);  // prefetch next step

        u64 a0 = 0ull, a1 = 0ull, a2 = 0ull, a3 = 0ull;
#pragma unroll
        for (int k = 0; k < 32; k += 4) {
            a0 = ffma2(w2[k + 0], h2[k + 0], a0);
            a1 = ffma2(w2[k + 1], h2[k + 1], a1);
            a2 = ffma2(w2[k + 2], h2[k + 2], a2);
            a3 = ffma2(w2[k + 3], h2[k + 3], a3);
        }
        u64 at = fadd2(fadd2(a0, a1), fadd2(a2, a3));
        float sx, sy; unpack2(at, sx, sy);
        g += sx + sy;

        float av = (j >= 128 && j < 192) ? tanh_fast(g) : sigmoidf_(g);
        act[j] = av;
        __syncthreads();

        if (j < 64) {
            c = act[64 + j] * c + act[j] * act[128 + j];
            float h = act[192 + j] * tanh_fast(c);
            h_sm[j] = h;
            hidden[(size_t)(s_cur * BSZ + b) * HID + dir * 64 + j] = h;
        }
        __syncthreads();
    }
}

// ---------------------------------------------------------------------------
// Kernel 3: action head + nonlinearities. One thread per (row, tape).
// params[row][t][8] = {rd0,rd1,rd2, wd0,wd1,wd2, rw_read, rw_write}
// ---------------------------------------------------------------------------
__global__ __launch_bounds__(256) void act_k(
    const float* __restrict__ hidden, const float* __restrict__ Wact,
    const float* __restrict__ bact, float* __restrict__ params)
{
    int gt  = blockIdx.x * 256 + threadIdx.x;   // 0 .. 32767
    int row = gt >> 1;
    int t   = gt & 1;

    const float4* h4 = (const float4*)(hidden + (size_t)row * HID);
    const float4* w4 = (const float4*)Wact;

    float acc[8];
#pragma unroll
    for (int jj = 0; jj < 8; jj++) acc[jj] = 0.0f;

#pragma unroll 4
    for (int k4 = 0; k4 < 32; k4++) {
        float4 h = __ldg(&h4[k4]);
#pragma unroll
        for (int jj = 0; jj < 8; jj++) {
            float4 w = __ldg(&w4[(t * 8 + jj) * 32 + k4]);
            acc[jj] += h.x * w.x + h.y * w.y + h.z * w.z + h.w * w.w;
        }
    }
#pragma unroll
    for (int jj = 0; jj < 8; jj++) acc[jj] += bact[t * 8 + jj];

    float out[8];
    float m = fmaxf(acc[0], fmaxf(acc[1], acc[2]));
    float e0 = __expf(acc[0] - m), e1 = __expf(acc[1] - m), e2 = __expf(acc[2] - m);
    float inv = 1.0f / (e0 + e1 + e2);
    out[0] = e0 * inv; out[1] = e1 * inv; out[2] = e2 * inv;
    m = fmaxf(acc[3], fmaxf(acc[4], acc[5]));
    e0 = __expf(acc[3] - m); e1 = __expf(acc[4] - m); e2 = __expf(acc[5] - m);
    inv = 1.0f / (e0 + e1 + e2);
    out[3] = e0 * inv; out[4] = e1 * inv; out[5] = e2 * inv;
    out[6] = sigmoidf_(acc[6]);
    out[7] = sigmoidf_(acc[7]);

    float4* p4 = (float4*)(params + (size_t)gt * 8);
    p4[0] = make_float4(out[0], out[1], out[2], out[3]);
    p4[1] = make_float4(out[4], out[5], out[6], out[7]);
}

// ---------------------------------------------------------------------------
// Kernel 4: tape scan. One block per (batch, tape) = 128 blocks, 256 threads.
// Tape lives in REGISTERS (16 u64/thread). 2 barriers/step. sw for step s+1
// computed in stage B of step s by the position warps (double-buffered).
//
// Thread map: q = tid>>5 (level group of 16), c2 = tid&31 (column pair).
//   stage A: owp/orp partials over register tape (positions via broadcast LDS,
//            wpos values saved to regs for stage C)
//   stage B: warp0: reduce partials, delta, readout;  warps4-7: new positions
//            into [nxt] buffers + sw partials for next step
//   stage C: register tape += wreg * delta   (no barrier — merges into next A)
// ---------------------------------------------------------------------------
__global__ __launch_bounds__(256) void tape_k(
    const float* __restrict__ values, const float* __restrict__ params,
    float* __restrict__ readouts,
    float* __restrict__ out_tape, float* __restrict__ out_rpos,
    float* __restrict__ out_wpos)
{
    int bt = blockIdx.x;        // b*2 + t
    int b  = bt >> 1;
    int t  = bt & 1;
    int tid = threadIdx.x;
    int q   = tid >> 5;         // 8 l-groups of 16
    int c2  = tid & 31;         // column pair

    __shared__ u64 wdup[2][TAPELEN], rdup[2][TAPELEN];
    __shared__ u64 pow_[8][32], por_[8][32];
    __shared__ u64 delta2[32];
    __shared__ float swp[2][4];

    int l0 = q * 16;
    u64 tp[16];
#pragma unroll
    for (int i = 0; i < 16; i++) tp[i] = 0ull;

    if (tid < TAPELEN) {
        float v = (tid == 0) ? 1.0f : 0.0f;
        wdup[0][tid] = dup2(v);
        rdup[0][tid] = dup2(v);
    }
    if (tid < 4) swp[0][tid] = (tid == 0) ? 1.0f : 0.0f;   // sw for step 0 = 1

    // prefetch step 0
    const float4* pbase = (const float4*)(params + ((size_t)b * 2 + t) * 8);
    float4 pp0 = __ldg(&pbase[0]);
    float4 pp1 = __ldg(&pbase[1]);
    u64 val2 = 0ull;
    if (tid < 32)
        val2 = __ldg((const u64*)(values + (size_t)b * HID + t * 64 + 2 * c2));
    __syncthreads();

    int cur = 0;
    for (int s = 0; s < S_LEN; s++) {
        int nxt = cur ^ 1;
        int sb  = s * BSZ + b;

        // --- stage A: dual dot products over register tape ---
        u64 wreg[16];
        u64 owp = 0ull, orp = 0ull;
#pragma unroll
        for (int i = 0; i < 16; i++) {
            wreg[i] = wdup[cur][l0 + i];
            u64 rr  = rdup[cur][l0 + i];
            owp = ffma2(tp[i], wreg[i], owp);
            orp = ffma2(tp[i], rr, orp);
        }
        pow_[q][c2] = owp;
        por_[q][c2] = orp;
        __syncthreads();

        // --- stage B ---
        if (tid < 32) {
            u64 ow2 = pow_[0][c2];
            u64 or2 = por_[0][c2];
#pragma unroll
            for (int qq = 1; qq < 8; qq++) {
                ow2 = fadd2(ow2, pow_[qq][c2]);
                or2 = fadd2(or2, por_[qq][c2]);
            }
            float sw = swp[cur][0] + swp[cur][1] + swp[cur][2] + swp[cur][3];
            float rw0 = pp1.z, rw1 = pp1.w;
            u64 d2 = fmul2(ffma2(ow2, dup2(-1.0f), val2), dup2(rw1));
            delta2[c2] = d2;
            u64 ro2 = fmul2(ffma2(d2, dup2(sw), or2), dup2(rw0));
            float rox, roy; unpack2(ro2, rox, roy);
            float2* ro = (float2*)(readouts + (size_t)sb * HID + t * 64 + 2 * c2);
            *ro = make_float2(rox, roy);
        } else if (tid >= 128) {
            int l = tid - 128;
            float rd0 = pp0.x, rd1 = pp0.y, rd2 = pp0.z;
            float wd0 = pp0.w, wd1 = pp1.x, wd2 = pp1.y;
            float rl, rp1, rm1, wl, d_;
            unpack2(rdup[cur][l], rl, d_);
            unpack2(rdup[cur][(l + 1) & 127], rp1, d_);
            unpack2(rdup[cur][(l - 1) & 127], rm1, d_);
            unpack2(wdup[cur][l], wl, d_);
            float nw = rp1 * wd0 + wl * wd1 + rm1 * wd2;
            float nr = rp1 * rd0 + rl * rd1 + rm1 * rd2;
            wdup[nxt][l] = dup2(nw);
            rdup[nxt][l] = dup2(nr);
            // sw for NEXT step
            float swpart = nw * nr;
#pragma unroll
            for (int off = 16; off; off >>= 1)
                swpart += __shfl_down_sync(0xffffffffu, swpart, off);
            if ((tid & 31) == 0) swp[nxt][q - 4] = swpart;
        }
        __syncthreads();

        // --- stage C: register tape update + prefetch (no barrier) ---
        u64 d2 = delta2[c2];
#pragma unroll
        for (int i = 0; i < 16; i++)
            tp[i] = ffma2(wreg[i], d2, tp[i]);

        if (s + 1 < S_LEN) {
            int sn = (s + 1) * BSZ + b;
            const float4* pb = (const float4*)(params + ((size_t)sn * 2 + t) * 8);
            pp0 = __ldg(&pb[0]);
            pp1 = __ldg(&pb[1]);
            if (tid < 32)
                val2 = __ldg((const u64*)(values + (size_t)sn * HID + t * 64 + 2 * c2));
        }
        cur = nxt;
    }

    // final state -> d_out  (positions in [cur], tape in registers)
    if (out_tape) {
#pragma unroll
        for (int i = 0; i < 16; i++) {
            int l = l0 + i;
            float x, y; unpack2(tp[i], x, y);
            float2* dst = (float2*)(out_tape + ((size_t)(l * BSZ + b) * 2 + t) * 64 + 2 * c2);
            *dst = make_float2(x, y);
        }
        if (tid < TAPELEN) {
            float rx, wx, d_;
            unpack2(rdup[cur][tid], rx, d_);
            unpack2(wdup[cur][tid], wx, d_);
            out_rpos[(size_t)(tid * BSZ + b) * 2 + t] = rx;
            out_wpos[(size_t)(tid * BSZ + b) * 2 + t] = wx;
        }
    }
}

// ---------------------------------------------------------------------------
// Launcher
// ---------------------------------------------------------------------------
extern "C" void kernel_launch(void* const* d_in, const int* in_sizes, int n_in,
                              void* d_out, int out_size)
{
    const float* inputs = (const float*)d_in[0];
    const float* W_ih_f = (const float*)d_in[2];
    const float* W_hh_f = (const float*)d_in[3];
    const float* b_ih_f = (const float*)d_in[4];
    const float* b_hh_f = (const float*)d_in[5];
    const float* W_ih_r = (const float*)d_in[6];
    const float* W_hh_r = (const float*)d_in[7];
    const float* b_ih_r = (const float*)d_in[8];
    const float* b_hh_r = (const float*)d_in[9];
    const float* W_act  = (const float*)d_in[10];
    const float* b_act  = (const float*)d_in[11];
    const float* W_val  = (const float*)d_in[12];
    const float* b_val  = (const float*)d_in[13];
    const float* W_out  = (const float*)d_in[14];
    const float* b_out  = (const float*)d_in[15];

    float* out = (float*)d_out;

    float *xf, *xr, *vals, *hid, *prm, *ro;
    cudaGetSymbolAddress((void**)&xf,   g_xproj_f);
    cudaGetSymbolAddress((void**)&xr,   g_xproj_r);
    cudaGetSymbolAddress((void**)&vals, g_values);
    cudaGetSymbolAddress((void**)&hid,  g_hidden);
    cudaGetSymbolAddress((void**)&prm,  g_params);
    cudaGetSymbolAddress((void**)&ro,   g_readout);

    // Phase 1: fused input projections (one launch, 1280 blocks)
    gemm_fused_in<<<dim3(10, N_ROWS / 128), 256>>>(
        inputs,
        W_ih_f, b_ih_f, b_hh_f,
        W_ih_r, b_ih_r, b_hh_r,
        W_val,  b_val,
        xf, xr, vals);

    // Phase 2: LSTM recurrence (128 blocks: batch x direction)
    lstm_k<<<128, 256>>>(xf, xr, W_hh_f, W_hh_r, hid);

    // Phase 3: action head
    act_k<<<128, 256>>>(hid, W_act, b_act, prm);

    // Phase 4: tape scan (128 blocks: batch x tape)
    bool full_out = (out_size >= OUT_TOTAL);
    tape_k<<<128, 256>>>(vals, prm, ro,
                         full_out ? out + OUT_TAPE_OFF : nullptr,
                         full_out ? out + OUT_RPOS_OFF : nullptr,
                         full_out ? out + OUT_WPOS_OFF : nullptr);

    // Phase 5: output projection straight into d_out
    gemm_k128<<<dim3(HID / 64, N_ROWS / 128), 256>>>(ro, W_out, b_out, out, HID);
}

// round 5
// speedup vs baseline: 1.4996x; 1.0080x over previous
#include <cuda_runtime.h>
#include <cuda_bf16.h>

// ---------------------------------------------------------------------------
// Problem constants (fixed by the dataset)
// ---------------------------------------------------------------------------
#define S_LEN   256
#define BSZ     64
#define IN_DIM  128
#define HID     128
#define NT      2
#define TAPELEN 128
#define DIM     64          // HID / NT
#define LH      64          // HID / 2
#define G4      256         // 4 * LH

#define N_ROWS  (S_LEN * BSZ)          // 16384

// d_out layout: outputs [S,B,HID], tape [TL,B,NT,DIM], rpos [TL,B,NT], wpos [TL,B,NT]
#define OUT_OUTPUTS_SZ  (S_LEN * BSZ * HID)                 // 2097152
#define OUT_TAPE_OFF    (OUT_OUTPUTS_SZ)
#define OUT_TAPE_SZ     (TAPELEN * BSZ * NT * DIM)          // 1048576
#define OUT_RPOS_OFF    (OUT_TAPE_OFF + OUT_TAPE_SZ)
#define OUT_POS_SZ      (TAPELEN * BSZ * NT)                // 16384
#define OUT_WPOS_OFF    (OUT_RPOS_OFF + OUT_POS_SZ)
#define OUT_TOTAL       (OUT_WPOS_OFF + OUT_POS_SZ)

typedef unsigned long long u64;

// ---------------------------------------------------------------------------
// f32x2 packed-math helpers (Blackwell FFMA2 path — PTX only)
// ---------------------------------------------------------------------------
__device__ __forceinline__ u64 pack2(float x, float y) {
    u64 r; asm("mov.b64 %0, {%1, %2};" : "=l"(r) : "f"(x), "f"(y)); return r;
}
__device__ __forceinline__ u64 dup2(float x) { return pack2(x, x); }
__device__ __forceinline__ void unpack2(u64 v, float& x, float& y) {
    asm("mov.b64 {%0, %1}, %2;" : "=f"(x), "=f"(y) : "l"(v));
}
__device__ __forceinline__ u64 ffma2(u64 a, u64 b, u64 c) {
    u64 d; asm("fma.rn.f32x2 %0, %1, %2, %3;" : "=l"(d) : "l"(a), "l"(b), "l"(c)); return d;
}
__device__ __forceinline__ u64 fadd2(u64 a, u64 b) {
    u64 d; asm("add.rn.f32x2 %0, %1, %2;" : "=l"(d) : "l"(a), "l"(b)); return d;
}
__device__ __forceinline__ u64 fmul2(u64 a, u64 b) {
    u64 d; asm("mul.rn.f32x2 %0, %1, %2;" : "=l"(d) : "l"(a), "l"(b)); return d;
}
__device__ __forceinline__ u64 shflx_u64(u64 v, int m) {
    float x, y; unpack2(v, x, y);
    x = __shfl_xor_sync(0xffffffffu, x, m);
    y = __shfl_xor_sync(0xffffffffu, y, m);
    return pack2(x, y);
}

__device__ __forceinline__ float sigmoidf_(float x) {
    return 1.0f / (1.0f + __expf(-x));
}
// tanh(x) = 2*sigmoid(2x) - 1  — MUFU-based, NaN-free at +/- inf
__device__ __forceinline__ float tanh_fast(float x) {
    return 2.0f / (1.0f + __expf(-2.0f * x)) - 1.0f;
}

// ---------------------------------------------------------------------------
// Scratch (device globals — no allocations allowed)
// ---------------------------------------------------------------------------
__device__ float g_xproj_f[N_ROWS * G4];     // 16.8 MB
__device__ float g_xproj_r[N_ROWS * G4];     // 16.8 MB
__device__ float g_values [N_ROWS * HID];    //  8.4 MB
__device__ float g_hidden [N_ROWS * HID];    //  8.4 MB
__device__ float g_params [N_ROWS * NT * 8]; //  1.0 MB
__device__ float g_readout[N_ROWS * HID];    //  8.4 MB

// ---------------------------------------------------------------------------
// GEMM core: C[M,N] = A[M,128] * B[N,128]^T + bias1[N] (+ bias2[N])
// BM=128, BN=64, BK=32, 256 threads, 8x4 microtile with row-paired f32x2 accs.
// ---------------------------------------------------------------------------
__device__ __forceinline__ void gemm_tile(
    const float* __restrict__ A, const float* __restrict__ B,
    const float* __restrict__ b1, const float* __restrict__ b2,
    float* __restrict__ C, int N, int row0, int col0)
{
    __shared__ __align__(16) float As[32][130];
    __shared__ __align__(16) float Bs[32][65];

    int tid = threadIdx.x;
    int tx = tid & 15;          // col group (4 cols)
    int ty = tid >> 4;          // row group (8 rows)

    const float4* A4 = (const float4*)A;
    const float4* B4 = (const float4*)B;

    u64 acc[4][4];
#pragma unroll
    for (int i = 0; i < 4; i++)
#pragma unroll
        for (int j = 0; j < 4; j++) acc[i][j] = 0ull;

#pragma unroll
    for (int kt = 0; kt < 4; kt++) {
#pragma unroll
        for (int rep = 0; rep < 4; rep++) {
            int e = tid + 256 * rep;
            int r = e >> 3, k4 = e & 7;
            float4 v = A4[(size_t)(row0 + r) * 32 + kt * 8 + k4];
            As[k4 * 4 + 0][r] = v.x; As[k4 * 4 + 1][r] = v.y;
            As[k4 * 4 + 2][r] = v.z; As[k4 * 4 + 3][r] = v.w;
        }
#pragma unroll
        for (int rep = 0; rep < 2; rep++) {
            int e = tid + 256 * rep;
            int r = e >> 3, k4 = e & 7;
            float4 v = B4[(size_t)(col0 + r) * 32 + kt * 8 + k4];
            Bs[k4 * 4 + 0][r] = v.x; Bs[k4 * 4 + 1][r] = v.y;
            Bs[k4 * 4 + 2][r] = v.z; Bs[k4 * 4 + 3][r] = v.w;
        }
        __syncthreads();

#pragma unroll
        for (int kk = 0; kk < 32; kk++) {
            u64 a2[4];
#pragma unroll
            for (int ip = 0; ip < 4; ip++)
                a2[ip] = *(const u64*)&As[kk][ty * 8 + 2 * ip];
#pragma unroll
            for (int j = 0; j < 4; j++) {
                u64 bd = dup2(Bs[kk][tx * 4 + j]);
#pragma unroll
                for (int ip = 0; ip < 4; ip++)
                    acc[ip][j] = ffma2(a2[ip], bd, acc[ip][j]);
            }
        }
        __syncthreads();
    }

#pragma unroll
    for (int j = 0; j < 4; j++) {
        int col = col0 + tx * 4 + j;
        float bv = b1[col] + (b2 ? b2[col] : 0.0f);
#pragma unroll
        for (int ip = 0; ip < 4; ip++) {
            float x, y; unpack2(acc[ip][j], x, y);
            int row = row0 + ty * 8 + 2 * ip;
            C[(size_t)row * N + col]       = x + bv;
            C[(size_t)(row + 1) * N + col] = y + bv;
        }
    }
}

// Fused input projections: 3 GEMMs (f-gates 256 cols, r-gates 256 cols, values 128 cols)
__global__ __launch_bounds__(256) void gemm_fused_in(
    const float* __restrict__ A,
    const float* __restrict__ Wf, const float* __restrict__ bf1, const float* __restrict__ bf2,
    const float* __restrict__ Wr, const float* __restrict__ br1, const float* __restrict__ br2,
    const float* __restrict__ Wv, const float* __restrict__ bv1,
    float* __restrict__ Cf, float* __restrict__ Cr, float* __restrict__ Cv)
{
    int cb = blockIdx.x;            // 0..9
    int row0 = blockIdx.y * 128;
    if (cb < 4)      gemm_tile(A, Wf, bf1, bf2,     Cf, G4,  row0, cb * 64);
    else if (cb < 8) gemm_tile(A, Wr, br1, br2,     Cr, G4,  row0, (cb - 4) * 64);
    else             gemm_tile(A, Wv, bv1, nullptr, Cv, HID, row0, (cb - 8) * 64);
}

__global__ __launch_bounds__(256) void gemm_k128(
    const float* __restrict__ A, const float* __restrict__ B,
    const float* __restrict__ b1, float* __restrict__ C, int N)
{
    gemm_tile(A, B, b1, nullptr, C, N, blockIdx.y * 128, blockIdx.x * 64);
}

// ---------------------------------------------------------------------------
// Kernel 2: bidirectional LSTM recurrence. One block per (batch, direction).
// Thread j owns gate j (W_hh row j resident in 32 f32x2 registers).
// xp pre-activation for step s+1 is prefetched during step s.
// ---------------------------------------------------------------------------
__global__ __launch_bounds__(256) void lstm_k(
    const float* __restrict__ xpf, const float* __restrict__ xpr,
    const float* __restrict__ Whh_f, const float* __restrict__ Whh_r,
    float* __restrict__ hidden)
{
    int b   = blockIdx.x & 63;
    int dir = blockIdx.x >> 6;
    int j   = threadIdx.x;

    const float* Whh = dir ? Whh_r : Whh_f;
    const float* xp  = dir ? xpr   : xpf;

    u64 w2[32];
    const u64* wrow = (const u64*)(Whh + j * 64);
#pragma unroll
    for (int k = 0; k < 32; k++) w2[k] = wrow[k];

    __shared__ __align__(16) float h_sm[64];
    __shared__ float act[256];
    if (j < 64) h_sm[j] = 0.0f;
    float c = 0.0f;
    __syncthreads();

    const u64* h2 = (const u64*)h_sm;
    const float* xbase = xp + (size_t)b * G4 + j;

    int s   = dir ? (S_LEN - 1) : 0;
    int stp = dir ? -1 : 1;
    float gn = __ldg(&xbase[(size_t)s * (BSZ * G4)]);   // prefetch step 0

    for (int ss = 0; ss < S_LEN; ss++) {
        float g = gn;
        int s_cur = s;
        s += stp;
        if (ss + 1 < S_LEN)
            gn = __ldg(&xbase[(size_t)s * (BSZ * G4)]);  // prefetch next step

        u64 a0 = 0ull, a1 = 0ull, a2 = 0ull, a3 = 0ull;
#pragma unroll
        for (int k = 0; k < 32; k += 4) {
            a0 = ffma2(w2[k + 0], h2[k + 0], a0);
            a1 = ffma2(w2[k + 1], h2[k + 1], a1);
            a2 = ffma2(w2[k + 2], h2[k + 2], a2);
            a3 = ffma2(w2[k + 3], h2[k + 3], a3);
        }
        u64 at = fadd2(fadd2(a0, a1), fadd2(a2, a3));
        float sx, sy; unpack2(at, sx, sy);
        g += sx + sy;

        float av = (j >= 128 && j < 192) ? tanh_fast(g) : sigmoidf_(g);
        act[j] = av;
        __syncthreads();

        if (j < 64) {
            c = act[64 + j] * c + act[j] * act[128 + j];
            float h = act[192 + j] * tanh_fast(c);
            h_sm[j] = h;
            hidden[(size_t)(s_cur * BSZ + b) * HID + dir * 64 + j] = h;
        }
        __syncthreads();
    }
}

// ---------------------------------------------------------------------------
// Kernel 3: action head + nonlinearities. One thread per (row, tape).
// params[row][t][8] = {rd0,rd1,rd2, wd0,wd1,wd2, rw_read, rw_write}
// ---------------------------------------------------------------------------
__global__ __launch_bounds__(256) void act_k(
    const float* __restrict__ hidden, const float* __restrict__ Wact,
    const float* __restrict__ bact, float* __restrict__ params)
{
    int gt  = blockIdx.x * 256 + threadIdx.x;   // 0 .. 32767
    int row = gt >> 1;
    int t   = gt & 1;

    const float4* h4 = (const float4*)(hidden + (size_t)row * HID);
    const float4* w4 = (const float4*)Wact;

    float acc[8];
#pragma unroll
    for (int jj = 0; jj < 8; jj++) acc[jj] = 0.0f;

#pragma unroll 4
    for (int k4 = 0; k4 < 32; k4++) {
        float4 h = __ldg(&h4[k4]);
#pragma unroll
        for (int jj = 0; jj < 8; jj++) {
            float4 w = __ldg(&w4[(t * 8 + jj) * 32 + k4]);
            acc[jj] += h.x * w.x + h.y * w.y + h.z * w.z + h.w * w.w;
        }
    }
#pragma unroll
    for (int jj = 0; jj < 8; jj++) acc[jj] += bact[t * 8 + jj];

    float out[8];
    float m = fmaxf(acc[0], fmaxf(acc[1], acc[2]));
    float e0 = __expf(acc[0] - m), e1 = __expf(acc[1] - m), e2 = __expf(acc[2] - m);
    float inv = 1.0f / (e0 + e1 + e2);
    out[0] = e0 * inv; out[1] = e1 * inv; out[2] = e2 * inv;
    m = fmaxf(acc[3], fmaxf(acc[4], acc[5]));
    e0 = __expf(acc[3] - m); e1 = __expf(acc[4] - m); e2 = __expf(acc[5] - m);
    inv = 1.0f / (e0 + e1 + e2);
    out[3] = e0 * inv; out[4] = e1 * inv; out[5] = e2 * inv;
    out[6] = sigmoidf_(acc[6]);
    out[7] = sigmoidf_(acc[7]);

    float4* p4 = (float4*)(params + (size_t)gt * 8);
    p4[0] = make_float4(out[0], out[1], out[2], out[3]);
    p4[1] = make_float4(out[4], out[5], out[6], out[7]);
}

// ---------------------------------------------------------------------------
// Kernel 4: tape scan — WARP-AUTONOMOUS. 1024 one-warp blocks, zero barriers,
// zero shared memory. Block = (b, t, cpgroup g). Warp = 4 lane-groups of 8;
// lane-group cg = lane>>3 owns column pair cp = 4g + cg across all 128 levels;
// lane r = lane&7 owns levels 16r .. 16r+15:
//   tape  : 16 u64 registers (f32x2 column pair per level)
//   wpos/rpos : 16 scalar f32 registers each
// Per step: dual dot + sw (reg FMAs) -> 3-round shfl_xor butterfly over the
// 8-lane group -> delta/readout -> register tape update -> position update
// (ring neighbors via 2 shuffles at the 16-level seams).
// ---------------------------------------------------------------------------
__global__ __launch_bounds__(32) void tape_k(
    const float* __restrict__ values, const float* __restrict__ params,
    float* __restrict__ readouts,
    float* __restrict__ out_tape, float* __restrict__ out_rpos,
    float* __restrict__ out_wpos)
{
    int bx = blockIdx.x;            // ((b*2 + t)*8 + g)
    int g  = bx & 7;
    int t  = (bx >> 3) & 1;
    int b  = bx >> 4;

    int lane = threadIdx.x;
    int cg   = lane >> 3;           // group within warp (0..3)
    int r    = lane & 7;            // lane-row within group
    int cp   = 4 * g + cg;          // column pair owned (0..31)
    int l0   = r * 16;              // first level owned

    // shuffle source lanes for ring neighbors (within the 8-lane group)
    int src_up = (lane & 24) | ((r + 1) & 7);   // holds level (l0+16) % 128
    int src_dn = (lane & 24) | ((r - 1) & 7);   // holds level (l0-1) & 127

    u64   tp[16];
    float wp[16], rp[16];
#pragma unroll
    for (int i = 0; i < 16; i++) {
        tp[i] = 0ull;
        float v = (r == 0 && i == 0) ? 1.0f : 0.0f;
        wp[i] = v; rp[i] = v;
    }

    // prefetch step 0
    const float* vbase = values + (size_t)b * HID + t * 64 + 2 * cp;
    const float4* pbase = (const float4*)(params + ((size_t)b * 2 + t) * 8);
    u64 val2 = __ldg((const u64*)vbase);
    float4 pp0 = __ldg(&pbase[0]);
    float4 pp1 = __ldg(&pbase[1]);

    for (int s = 0; s < S_LEN; s++) {
        int sb = s * BSZ + b;

        // --- dual dot products + sw partial (all register) ---
        u64 owp = 0ull, orp = 0ull;
        float swl = 0.0f;
#pragma unroll
        for (int i = 0; i < 16; i++) {
            owp = ffma2(tp[i], dup2(wp[i]), owp);
            orp = ffma2(tp[i], dup2(rp[i]), orp);
            swl = fmaf(wp[i], rp[i], swl);
        }
        // --- butterfly reduce over the 8-lane group ---
#pragma unroll
        for (int m = 1; m <= 4; m <<= 1) {
            owp = fadd2(owp, shflx_u64(owp, m));
            orp = fadd2(orp, shflx_u64(orp, m));
            swl += __shfl_xor_sync(0xffffffffu, swl, m);
        }

        // --- delta, readout ---
        float rw0 = pp1.z, rw1 = pp1.w;
        u64 d2  = fmul2(ffma2(owp, dup2(-1.0f), val2), dup2(rw1));
        u64 ro2 = fmul2(ffma2(d2, dup2(swl), orp), dup2(rw0));
        if (r == 0) {
            float rox, roy; unpack2(ro2, rox, roy);
            *(float2*)(readouts + (size_t)sb * HID + t * 64 + 2 * cp) =
                make_float2(rox, roy);
        }

        // --- prefetch next step (overlaps with update math) ---
        float4 np0 = pp0, np1 = pp1;
        u64 nval = val2;
        if (s + 1 < S_LEN) {
            int sn = (s + 1) * BSZ + b;
            nval = __ldg((const u64*)(values + (size_t)sn * HID + t * 64 + 2 * cp));
            const float4* pb = (const float4*)(params + ((size_t)sn * 2 + t) * 8);
            np0 = __ldg(&pb[0]);
            np1 = __ldg(&pb[1]);
        }

        // --- tape update (register rank-1) ---
#pragma unroll
        for (int i = 0; i < 16; i++)
            tp[i] = ffma2(dup2(wp[i]), d2, tp[i]);

        // --- position update (ring neighbors via 2 shuffles) ---
        float rtop = __shfl_sync(0xffffffffu, rp[0],  src_up);  // rpos[l0+16 mod 128]
        float rbot = __shfl_sync(0xffffffffu, rp[15], src_dn);  // rpos[l0-1  mod 128]
        float rd0 = pp0.x, rd1 = pp0.y, rd2 = pp0.z;
        float wd0 = pp0.w, wd1 = pp1.x, wd2 = pp1.y;

        float prev = rbot;
#pragma unroll
        for (int i = 0; i < 16; i++) {
            float cur  = rp[i];
            float next = (i < 15) ? rp[i + 1] : rtop;
            // wpos'[l] = rpos[l+1]*wd0 + wpos[l]*wd1 + rpos[l-1]*wd2
            wp[i] = fmaf(next, wd0, fmaf(wp[i], wd1, prev * wd2));
            // rpos'[l] = rpos[l+1]*rd0 + rpos[l]*rd1 + rpos[l-1]*rd2
            rp[i] = fmaf(next, rd0, fmaf(cur,  rd1, prev * rd2));
            prev = cur;
        }

        val2 = nval; pp0 = np0; pp1 = np1;
    }

    // --- final state -> d_out ---
    if (out_tape) {
#pragma unroll
        for (int i = 0; i < 16; i++) {
            int l = l0 + i;
            float x, y; unpack2(tp[i], x, y);
            *(float2*)(out_tape + ((size_t)(l * BSZ + b) * 2 + t) * 64 + 2 * cp) =
                make_float2(x, y);
        }
        if (cg == 0) {      // one group writes the (replicated) positions
#pragma unroll
            for (int i = 0; i < 16; i++) {
                int l = l0 + i;
                out_rpos[(size_t)(l * BSZ + b) * 2 + t] = rp[i];
                out_wpos[(size_t)(l * BSZ + b) * 2 + t] = wp[i];
            }
        }
    }
}

// ---------------------------------------------------------------------------
// Launcher
// ---------------------------------------------------------------------------
extern "C" void kernel_launch(void* const* d_in, const int* in_sizes, int n_in,
                              void* d_out, int out_size)
{
    const float* inputs = (const float*)d_in[0];
    const float* W_ih_f = (const float*)d_in[2];
    const float* W_hh_f = (const float*)d_in[3];
    const float* b_ih_f = (const float*)d_in[4];
    const float* b_hh_f = (const float*)d_in[5];
    const float* W_ih_r = (const float*)d_in[6];
    const float* W_hh_r = (const float*)d_in[7];
    const float* b_ih_r = (const float*)d_in[8];
    const float* b_hh_r = (const float*)d_in[9];
    const float* W_act  = (const float*)d_in[10];
    const float* b_act  = (const float*)d_in[11];
    const float* W_val  = (const float*)d_in[12];
    const float* b_val  = (const float*)d_in[13];
    const float* W_out  = (const float*)d_in[14];
    const float* b_out  = (const float*)d_in[15];

    float* out = (float*)d_out;

    float *xf, *xr, *vals, *hid, *prm, *ro;
    cudaGetSymbolAddress((void**)&xf,   g_xproj_f);
    cudaGetSymbolAddress((void**)&xr,   g_xproj_r);
    cudaGetSymbolAddress((void**)&vals, g_values);
    cudaGetSymbolAddress((void**)&hid,  g_hidden);
    cudaGetSymbolAddress((void**)&prm,  g_params);
    cudaGetSymbolAddress((void**)&ro,   g_readout);

    // Phase 1: fused input projections (one launch, 1280 blocks)
    gemm_fused_in<<<dim3(10, N_ROWS / 128), 256>>>(
        inputs,
        W_ih_f, b_ih_f, b_hh_f,
        W_ih_r, b_ih_r, b_hh_r,
        W_val,  b_val,
        xf, xr, vals);

    // Phase 2: LSTM recurrence (128 blocks: batch x direction)
    lstm_k<<<128, 256>>>(xf, xr, W_hh_f, W_hh_r, hid);

    // Phase 3: action head
    act_k<<<128, 256>>>(hid, W_act, b_act, prm);

    // Phase 4: tape scan (1024 one-warp blocks: batch x tape x colgroup)
    bool full_out = (out_size >= OUT_TOTAL);
    tape_k<<<1024, 32>>>(vals, prm, ro,
                         full_out ? out + OUT_TAPE_OFF : nullptr,
                         full_out ? out + OUT_RPOS_OFF : nullptr,
                         full_out ? out + OUT_WPOS_OFF : nullptr);

    // Phase 5: output projection straight into d_out
    gemm_k128<<<dim3(HID / 64, N_ROWS / 128), 256>>>(ro, W_out, b_out, out, HID);
}